// round 14
// baseline (speedup 1.0000x reference)
#include <cuda_runtime.h>
#include <cuda_bf16.h>
#include <cstdint>

#define B_   2
#define S_   2048
#define D_   1024
#define H_   16
#define DH_  64
#define FF_  2048
#define N_   (B_*S_)     // 4096
#define EPS_ 1e-6f

#define FLAG_RELU 1

// ---------------- scratch (allocation-free) ----------------
__device__ float g_q[N_ * D_];     // [B,H,S,Dh]
__device__ float g_k[N_ * D_];
__device__ float g_v[N_ * D_];
__device__ float g_ctx[N_ * D_];   // [N, D]
__device__ float g_x0[N_ * D_];
__device__ float g_x1[N_ * D_];
__device__ float g_ff[N_ * FF_];
__device__ uint32_t g_mflags[N_];  // [b*S + qrow] -> bit per 64-key tile: 1 = all nonzero

// ---------------- helpers ----------------
__device__ __forceinline__ uint32_t f2tf32(float x) {
    uint32_t r;
    asm("cvt.rna.tf32.f32 %0, %1;" : "=r"(r) : "f"(x));
    return r;
}

__device__ __forceinline__ uint32_t pack_bf16(float lo, float hi) {
    uint32_t r;
    asm("cvt.rn.bf16x2.f32 %0, %1, %2;" : "=r"(r) : "f"(hi), "f"(lo));
    return r;
}

__device__ __forceinline__ void mma_tf32(float c[4], uint32_t a0, uint32_t a1, uint32_t a2, uint32_t a3,
                                         uint32_t b0, uint32_t b1) {
    asm volatile("mma.sync.aligned.m16n8k8.row.col.f32.tf32.tf32.f32 "
                 "{%0,%1,%2,%3}, {%4,%5,%6,%7}, {%8,%9}, {%0,%1,%2,%3};"
                 : "+f"(c[0]), "+f"(c[1]), "+f"(c[2]), "+f"(c[3])
                 : "r"(a0), "r"(a1), "r"(a2), "r"(a3), "r"(b0), "r"(b1));
}

__device__ __forceinline__ void mma_bf16(float c[4], uint32_t a0, uint32_t a1, uint32_t a2, uint32_t a3,
                                         uint32_t b0, uint32_t b1) {
    asm volatile("mma.sync.aligned.m16n8k16.row.col.f32.bf16.bf16.f32 "
                 "{%0,%1,%2,%3}, {%4,%5,%6,%7}, {%8,%9}, {%0,%1,%2,%3};"
                 : "+f"(c[0]), "+f"(c[1]), "+f"(c[2]), "+f"(c[3])
                 : "r"(a0), "r"(a1), "r"(a2), "r"(a3), "r"(b0), "r"(b1));
}

__device__ __forceinline__ void cp_async16(uint32_t dst, const void* src) {
    asm volatile("cp.async.cg.shared.global [%0], [%1], 16;" :: "r"(dst), "l"(src));
}
__device__ __forceinline__ void cp_commit() { asm volatile("cp.async.commit_group;" ::: "memory"); }
__device__ __forceinline__ void cp_wait0()  { asm volatile("cp.async.wait_group 0;" ::: "memory"); }

// fast exp on the FMA pipe (no MUFU)
__device__ __forceinline__ float fast_exp(float x) {
    float y = fmaxf(x * 1.4426950408889634f, -126.0f);
    float t = y + 12582912.0f;
    int   n = __float_as_int(t) - 0x4B400000;
    float f = y - (t - 12582912.0f);
    float p = 1.3333558146e-3f;
    p = fmaf(p, f, 9.6181291e-3f);
    p = fmaf(p, f, 5.5504108664e-2f);
    p = fmaf(p, f, 2.4022650696e-1f);
    p = fmaf(p, f, 6.9314718056e-1f);
    p = fmaf(p, f, 1.0f);
    return p * __int_as_float((n + 127) << 23);
}

// ---------------- mask flags precompute: one warp per (b,row) ----------------
__global__ void maskflags_kernel(const int* __restrict__ mask, uint32_t* __restrict__ flags)
{
    const int gw = (blockIdx.x * blockDim.x + threadIdx.x) >> 5;   // row index 0..N_-1
    const int lane = threadIdx.x & 31;
    if (gw >= N_) return;
    const int* row = mask + (size_t)gw * S_;
    uint32_t bits = 0;
#pragma unroll
    for (int kt = 0; kt < 32; kt++) {
        int2 v = *(const int2*)&row[kt * 64 + lane * 2];
        int nz = (v.x != 0) & (v.y != 0);
        nz = __all_sync(0xffffffffu, nz);
        bits |= (uint32_t)nz << kt;
    }
    if (lane == 0) flags[gw] = bits;
}

// ---------------- GEMM: BK=32, 2-stage distance-1 cp.async, conflict-free LDS.64 ----------------
// pitch 40 words: pair-bank m = (20g+tg) mod 16 = 4g+tg, all distinct per phase.
// k-slot permutation: slot tg <- k=2tg, slot tg+4 <- k=2tg+1 (A and B identical -> exact)
// Pipeline: wait0 + single sync per iter; load kt+1 targets OTHER buffer after sync (race-free,
// same pattern as flash kernel). NOT distance-2 (r13 bug: aliased the live buffer).
#define GPITCH 40
#define GSTAGES 2
#define GSTAGE_U32 (128 * GPITCH)
#define GEMM_SMEM (GSTAGES * 2 * GSTAGE_U32 * 4)   // 81920 B

struct GemmCtx {
    int t, wm, wn, g, tg, lrr, kq;
};

__device__ __forceinline__ void gemm_stage_load(
    const float* Aptr0, const float* Aptr1, const float* Wptr0, const float* Wptr1,
    uint32_t aBase, uint32_t wBase, uint32_t off0, uint32_t off1, int k0)
{
    cp_async16(aBase + off0,      Aptr0 + k0);
    cp_async16(aBase + off0 + 16, Aptr0 + k0 + 4);
    cp_async16(aBase + off1,      Aptr1 + k0);
    cp_async16(aBase + off1 + 16, Aptr1 + k0 + 4);
    cp_async16(wBase + off0,      Wptr0 + k0);
    cp_async16(wBase + off0 + 16, Wptr0 + k0 + 4);
    cp_async16(wBase + off1,      Wptr1 + k0);
    cp_async16(wBase + off1 + 16, Wptr1 + k0 + 4);
}

__device__ __forceinline__ void gemm_mainloop(
    const float* Aptr0, const float* Aptr1, const float* Wptr0, const float* Wptr1,
    uint32_t* Asm, uint32_t* Wsm, const GemmCtx& cx, int K, float acc[4][4][4])
{
    const uint32_t aBase = (uint32_t)__cvta_generic_to_shared(Asm);
    const uint32_t wBase = (uint32_t)__cvta_generic_to_shared(Wsm);
    // loader: row lrr (+64), cols kq*8 .. kq*8+7 (two float4)
    const uint32_t off0 = (cx.lrr * GPITCH + cx.kq * 8) * 4;
    const uint32_t off1 = ((cx.lrr + 64) * GPITCH + cx.kq * 8) * 4;
    const int KT = K >> 5;   // BK = 32

    // prologue: stage 0 into buffer 0
    gemm_stage_load(Aptr0, Aptr1, Wptr0, Wptr1, aBase, wBase, off0, off1, 0);
    cp_commit();

    for (int kt = 0; kt < KT; kt++) {
        cp_wait0();          // stage kt resident in buffer kt&1
        __syncthreads();     // all warps done with iteration kt-1 (reads of buffer (kt+1)&1 finished)
        const uint32_t* As_ = Asm + (kt & 1) * GSTAGE_U32;
        const uint32_t* Ws_ = Wsm + (kt & 1) * GSTAGE_U32;

        if (kt + 1 < KT) {   // prefetch stage kt+1 into the OTHER buffer (just freed)
            const uint32_t sb = ((kt + 1) & 1) * GSTAGE_U32 * 4;
            gemm_stage_load(Aptr0, Aptr1, Wptr0, Wptr1,
                            aBase + sb, wBase + sb, off0, off1, (kt + 1) * 32);
            cp_commit();
        }

#pragma unroll
        for (int ks = 0; ks < 4; ks++) {
            const int kb = ks * 8 + 2 * cx.tg;
            uint2 alo[4], ahi[4], bfp[4];
#pragma unroll
            for (int mi = 0; mi < 4; mi++) {
                const int nb = cx.wm * 64 + mi * 16;
                alo[mi] = *(const uint2*)&As_[(nb + cx.g) * GPITCH + kb];
                ahi[mi] = *(const uint2*)&As_[(nb + cx.g + 8) * GPITCH + kb];
            }
#pragma unroll
            for (int ni = 0; ni < 4; ni++) {
                const int mb = cx.wn * 32 + ni * 8;
                bfp[ni] = *(const uint2*)&Ws_[(mb + cx.g) * GPITCH + kb];
            }
#pragma unroll
            for (int mi = 0; mi < 4; mi++)
#pragma unroll
                for (int ni = 0; ni < 4; ni++)
                    mma_tf32(acc[mi][ni], alo[mi].x, ahi[mi].x, alo[mi].y, ahi[mi].y,
                             bfp[ni].x, bfp[ni].y);
        }
    }
    __syncthreads();
}

__device__ __forceinline__ GemmCtx make_ctx(int t) {
    GemmCtx cx;
    cx.t = t;
    int w = t >> 5;
    cx.wm = w >> 2;
    cx.wn = w & 3;
    int lane = t & 31;
    cx.g  = lane >> 2;
    cx.tg = lane & 3;
    cx.lrr = t >> 2;
    cx.kq  = t & 3;
    return cx;
}

// ---------------- generic GEMM (Wo, FF1, FF2) ----------------
__global__ __launch_bounds__(256, 2)
void gemm_tf32(const float* __restrict__ A, const float* __restrict__ W,
               const float* __restrict__ bias, const float* __restrict__ residual,
               float* __restrict__ C, int N, int M, int K, int flags)
{
    extern __shared__ uint32_t gsm[];
    uint32_t* Asm = gsm;
    uint32_t* Wsm = gsm + GSTAGES * GSTAGE_U32;

    GemmCtx cx = make_ctx(threadIdx.x);
    const int n0 = blockIdx.y * 128, m0 = blockIdx.x * 128;

    float acc[4][4][4];
#pragma unroll
    for (int mi = 0; mi < 4; mi++)
#pragma unroll
        for (int ni = 0; ni < 4; ni++)
#pragma unroll
            for (int c = 0; c < 4; c++) acc[mi][ni][c] = 0.f;

    gemm_mainloop(A + (size_t)(n0 + cx.lrr) * K + cx.kq * 8,
                  A + (size_t)(n0 + cx.lrr + 64) * K + cx.kq * 8,
                  W + (size_t)(m0 + cx.lrr) * K + cx.kq * 8,
                  W + (size_t)(m0 + cx.lrr + 64) * K + cx.kq * 8,
                  Asm, Wsm, cx, K, acc);

#pragma unroll
    for (int mi = 0; mi < 4; mi++) {
#pragma unroll
        for (int ni = 0; ni < 4; ni++) {
#pragma unroll
            for (int c = 0; c < 4; c++) {
                int n = n0 + cx.wm * 64 + mi * 16 + cx.g + ((c >> 1) ? 8 : 0);
                int m = m0 + cx.wn * 32 + ni * 8 + cx.tg * 2 + (c & 1);
                float v = acc[mi][ni][c] + bias[m];
                if (residual) v += residual[(size_t)n * M + m];
                if (flags & FLAG_RELU) v = fmaxf(v, 0.f);
                C[(size_t)n * M + m] = v;
            }
        }
    }
}

// ---------------- fused QKV GEMM: gridDim.z = 3 selects projection ----------------
__global__ __launch_bounds__(256, 2)
void gemm_qkv(const float* __restrict__ A,
              const float* __restrict__ Wq, const float* __restrict__ Wk, const float* __restrict__ Wv,
              const float* __restrict__ bq, const float* __restrict__ bk, const float* __restrict__ bv,
              float* __restrict__ Cq, float* __restrict__ Ck, float* __restrict__ Cv)
{
    extern __shared__ uint32_t gsm[];
    uint32_t* Asm = gsm;
    uint32_t* Wsm = gsm + GSTAGES * GSTAGE_U32;

    const int z = blockIdx.z;
    const float* W    = (z == 0) ? Wq : (z == 1) ? Wk : Wv;
    const float* bias = (z == 0) ? bq : (z == 1) ? bk : bv;
    float* C          = (z == 0) ? Cq : (z == 1) ? Ck : Cv;

    GemmCtx cx = make_ctx(threadIdx.x);
    const int n0 = blockIdx.y * 128, m0 = blockIdx.x * 128;
    const int K = D_;

    float acc[4][4][4];
#pragma unroll
    for (int mi = 0; mi < 4; mi++)
#pragma unroll
        for (int ni = 0; ni < 4; ni++)
#pragma unroll
            for (int c = 0; c < 4; c++) acc[mi][ni][c] = 0.f;

    gemm_mainloop(A + (size_t)(n0 + cx.lrr) * K + cx.kq * 8,
                  A + (size_t)(n0 + cx.lrr + 64) * K + cx.kq * 8,
                  W + (size_t)(m0 + cx.lrr) * K + cx.kq * 8,
                  W + (size_t)(m0 + cx.lrr + 64) * K + cx.kq * 8,
                  Asm, Wsm, cx, K, acc);

    // epilogue with head-layout scatter: [B,H,S,Dh]
#pragma unroll
    for (int mi = 0; mi < 4; mi++) {
#pragma unroll
        for (int ni = 0; ni < 4; ni++) {
#pragma unroll
            for (int c = 0; c < 4; c++) {
                int n = n0 + cx.wm * 64 + mi * 16 + cx.g + ((c >> 1) ? 8 : 0);
                int m = m0 + cx.wn * 32 + ni * 8 + cx.tg * 2 + (c & 1);
                float v = acc[mi][ni][c] + bias[m];
                int b = n >> 11, s = n & 2047;
                int h = m >> 6,  dh = m & 63;
                C[(((size_t)(b * H_ + h)) * S_ + s) * DH_ + dh] = v;
            }
        }
    }
}

// ---------------- flash attention: double-buffered K/V + flag-gated mask (r12 proven) ----------------
#define FAP 72
#define VPP 36
#define KBUF_U32 (64 * FAP)
#define VBUF_U32 (64 * VPP)
#define FA_SMEM ((128 * FAP + 2 * KBUF_U32 + 2 * VBUF_U32) * 4)   // 92160 B

__global__ __launch_bounds__(256, 2)
void flash_tf32(const float* __restrict__ q, const float* __restrict__ k,
                const float* __restrict__ v, const int* __restrict__ mask,
                const uint32_t* __restrict__ mflags, float* __restrict__ ctx)
{
    extern __shared__ uint32_t sm4[];
    uint32_t* Qs   = sm4;                            // [128 q][d] tf32
    uint32_t* Ks   = sm4 + 128 * FAP;                // [2][64 kc][d] raw f32
    uint32_t* VsTb = sm4 + 128 * FAP + 2 * KBUF_U32; // [2][64 d][32 kp] bf16x2

    const int t = threadIdx.x;
    const int w = t >> 5, lane = t & 31;
    const int g = lane >> 2, tg = lane & 3;
    const int qb = w * 16;
    const int bh = blockIdx.y, b = bh >> 4, h = bh & 15;
    const int q0 = blockIdx.x * 128;
    const float* qh = q + (size_t)bh * S_ * DH_;
    const float* kh = k + (size_t)bh * S_ * DH_;
    const float* vh = v + (size_t)bh * S_ * DH_;
    const int* maskb = mask + (size_t)b * S_ * S_;

    const uint32_t ksBase = (uint32_t)__cvta_generic_to_shared(Ks);

    const int krow = t & 63;            // K loader: row, 4 threads/row
    const int kcol = (t >> 6) * 16;
    const int kp = t & 31;              // V loader: keypair
    const int db = (t >> 5) * 8;

    const uint32_t bits0 = mflags[b * S_ + q0 + qb + g];
    const uint32_t bits1 = mflags[b * S_ + q0 + qb + g + 8];

    {   // Q tile (128x64) -> smem tf32 (rna-rounded, loaded once)
        const int lr = t >> 1, lc = (t & 1) * 32;
        const float4* src4 = (const float4*)(qh + (size_t)(q0 + lr) * 64 + lc);
#pragma unroll
        for (int i = 0; i < 8; i++) {
            float4 a = src4[i];
            uint4 u = { f2tf32(a.x), f2tf32(a.y), f2tf32(a.z), f2tf32(a.w) };
            *(uint4*)&Qs[lr * FAP + lc + i * 4] = u;
        }
    }

    // prologue: tile 0 into buffer 0
    {
        const float* ksrc = kh + (size_t)krow * 64 + kcol;
        const uint32_t kdst = ksBase + (krow * FAP + kcol) * 4;
#pragma unroll
        for (int i = 0; i < 4; i++) cp_async16(kdst + i * 16, ksrc + i * 4);
        cp_commit();
        const float4* v0p = (const float4*)(vh + (size_t)(2 * kp) * 64 + db);
        const float4* v1p = (const float4*)(vh + (size_t)(2 * kp + 1) * 64 + db);
        float4 e0 = v0p[0], e1 = v0p[1], o0 = v1p[0], o1 = v1p[1];
        uint32_t* Vb = VsTb;
        Vb[(db + 0) * VPP + kp] = pack_bf16(e0.x, o0.x);
        Vb[(db + 1) * VPP + kp] = pack_bf16(e0.y, o0.y);
        Vb[(db + 2) * VPP + kp] = pack_bf16(e0.z, o0.z);
        Vb[(db + 3) * VPP + kp] = pack_bf16(e0.w, o0.w);
        Vb[(db + 4) * VPP + kp] = pack_bf16(e1.x, o1.x);
        Vb[(db + 5) * VPP + kp] = pack_bf16(e1.y, o1.y);
        Vb[(db + 6) * VPP + kp] = pack_bf16(e1.z, o1.z);
        Vb[(db + 7) * VPP + kp] = pack_bf16(e1.w, o1.w);
        cp_wait0();
    }
    __syncthreads();

    float outac[8][4];
#pragma unroll
    for (int j = 0; j < 8; j++)
#pragma unroll
        for (int c = 0; c < 4; c++) outac[j][c] = 0.f;
    float mrow0 = -1e30f, mrow1 = -1e30f;
    float lrow0 = 0.f, lrow1 = 0.f;

    const int NT = S_ / 64;   // 32
    for (int it = 0; it < NT; it++) {
        const int buf = it & 1;
        const uint32_t* Kb = Ks + buf * KBUF_U32;
        const uint32_t* Vb = VsTb + buf * VBUF_U32;
        const bool more = (it + 1 < NT);

        float4 e0, e1, o0, o1;
        if (more) {
            const int kn = (it + 1) * 64;
            const float* ksrc = kh + (size_t)(kn + krow) * 64 + kcol;
            const uint32_t kdst = ksBase + ((buf ^ 1) * KBUF_U32 + krow * FAP + kcol) * 4;
#pragma unroll
            for (int i = 0; i < 4; i++) cp_async16(kdst + i * 16, ksrc + i * 4);
            cp_commit();
            const float4* v0p = (const float4*)(vh + (size_t)(kn + 2 * kp) * 64 + db);
            const float4* v1p = (const float4*)(vh + (size_t)(kn + 2 * kp + 1) * 64 + db);
            e0 = v0p[0]; e1 = v0p[1]; o0 = v1p[0]; o1 = v1p[1];
        }

        // S = Q K^T  (tf32; conflict-free LDS.64 fragments, k-slot permuted)
        float sa[8][4];
#pragma unroll
        for (int j = 0; j < 8; j++)
#pragma unroll
            for (int c = 0; c < 4; c++) sa[j][c] = 0.f;
#pragma unroll
        for (int kc = 0; kc < 8; kc++) {
            const int kb = kc * 8 + 2 * tg;
            uint2 qlo = *(const uint2*)&Qs[(qb + g) * FAP + kb];
            uint2 qhi = *(const uint2*)&Qs[(qb + g + 8) * FAP + kb];
#pragma unroll
            for (int j = 0; j < 8; j++) {
                uint2 kf = *(const uint2*)&Kb[(j * 8 + g) * FAP + kb];
                mma_tf32(sa[j], qlo.x, qhi.x, qlo.y, qhi.y, kf.x, kf.y);
            }
        }

        if (more) {
            uint32_t* Vn = VsTb + (buf ^ 1) * VBUF_U32;
            Vn[(db + 0) * VPP + kp] = pack_bf16(e0.x, o0.x);
            Vn[(db + 1) * VPP + kp] = pack_bf16(e0.y, o0.y);
            Vn[(db + 2) * VPP + kp] = pack_bf16(e0.z, o0.z);
            Vn[(db + 3) * VPP + kp] = pack_bf16(e0.w, o0.w);
            Vn[(db + 4) * VPP + kp] = pack_bf16(e1.x, o1.x);
            Vn[(db + 5) * VPP + kp] = pack_bf16(e1.y, o1.y);
            Vn[(db + 6) * VPP + kp] = pack_bf16(e1.z, o1.z);
            Vn[(db + 7) * VPP + kp] = pack_bf16(e1.w, o1.w);
        }

        // scale + mask (flag-gated)
        const bool allok = (((bits0 >> it) & (bits1 >> it)) & 1u) != 0u;
        if (allok) {
#pragma unroll
            for (int j = 0; j < 8; j++) {
                sa[j][0] *= 0.125f; sa[j][1] *= 0.125f;
                sa[j][2] *= 0.125f; sa[j][3] *= 0.125f;
            }
        } else {
            const int k0 = it * 64;
            const size_t mrow_a = (size_t)(q0 + qb + g) * S_ + k0;
            const size_t mrow_b = (size_t)(q0 + qb + g + 8) * S_ + k0;
#pragma unroll
            for (int j = 0; j < 8; j++) {
                int col = j * 8 + tg * 2;
                int2 m0 = *(const int2*)&maskb[mrow_a + col];
                int2 m1 = *(const int2*)&maskb[mrow_b + col];
                sa[j][0] = m0.x ? sa[j][0] * 0.125f : -1e9f;
                sa[j][1] = m0.y ? sa[j][1] * 0.125f : -1e9f;
                sa[j][2] = m1.x ? sa[j][2] * 0.125f : -1e9f;
                sa[j][3] = m1.y ? sa[j][3] * 0.125f : -1e9f;
            }
        }

        // online softmax (rows g, g+8), quad reduce
        float mx0 = -1e30f, mx1 = -1e30f;
#pragma unroll
        for (int j = 0; j < 8; j++) {
            mx0 = fmaxf(mx0, fmaxf(sa[j][0], sa[j][1]));
            mx1 = fmaxf(mx1, fmaxf(sa[j][2], sa[j][3]));
        }
        mx0 = fmaxf(mx0, __shfl_xor_sync(0xffffffffu, mx0, 1));
        mx0 = fmaxf(mx0, __shfl_xor_sync(0xffffffffu, mx0, 2));
        mx1 = fmaxf(mx1, __shfl_xor_sync(0xffffffffu, mx1, 1));
        mx1 = fmaxf(mx1, __shfl_xor_sync(0xffffffffu, mx1, 2));

        float mn0 = fmaxf(mrow0, mx0), mn1 = fmaxf(mrow1, mx1);
        float cr0 = fast_exp(mrow0 - mn0), cr1 = fast_exp(mrow1 - mn1);
        mrow0 = mn0; mrow1 = mn1;

        float rs0 = 0.f, rs1 = 0.f;
#pragma unroll
        for (int j = 0; j < 8; j++) {
            sa[j][0] = fast_exp(sa[j][0] - mn0);
            sa[j][1] = fast_exp(sa[j][1] - mn0);
            sa[j][2] = fast_exp(sa[j][2] - mn1);
            sa[j][3] = fast_exp(sa[j][3] - mn1);
            rs0 += sa[j][0] + sa[j][1];
            rs1 += sa[j][2] + sa[j][3];
        }
        rs0 += __shfl_xor_sync(0xffffffffu, rs0, 1);
        rs0 += __shfl_xor_sync(0xffffffffu, rs0, 2);
        rs1 += __shfl_xor_sync(0xffffffffu, rs1, 1);
        rs1 += __shfl_xor_sync(0xffffffffu, rs1, 2);
        lrow0 = lrow0 * cr0 + rs0;
        lrow1 = lrow1 * cr1 + rs1;

#pragma unroll
        for (int j = 0; j < 8; j++) {
            outac[j][0] *= cr0; outac[j][1] *= cr0;
            outac[j][2] *= cr1; outac[j][3] *= cr1;
        }

        // out += P V  — P packed from registers (bf16), V from current buffer
#pragma unroll
        for (int s = 0; s < 4; s++) {
            uint32_t a0 = pack_bf16(sa[2*s][0],   sa[2*s][1]);
            uint32_t a1 = pack_bf16(sa[2*s][2],   sa[2*s][3]);
            uint32_t a2 = pack_bf16(sa[2*s+1][0], sa[2*s+1][1]);
            uint32_t a3 = pack_bf16(sa[2*s+1][2], sa[2*s+1][3]);
            const int kpb = 8 * s;
#pragma unroll
            for (int j = 0; j < 8; j++) {
                uint32_t b0 = Vb[(j * 8 + g) * VPP + kpb + tg];
                uint32_t b1 = Vb[(j * 8 + g) * VPP + kpb + tg + 4];
                mma_bf16(outac[j], a0, a1, a2, a3, b0, b1);
            }
        }

        if (more) cp_wait0();
        __syncthreads();
    }

    // epilogue
    float i0 = 1.f / lrow0, i1 = 1.f / lrow1;
    const int nrow = b * S_ + q0 + qb + g;
    const int hb = h * 64;
#pragma unroll
    for (int j = 0; j < 8; j++) {
        float2 o0 = { outac[j][0] * i0, outac[j][1] * i0 };
        *(float2*)&ctx[(size_t)nrow * D_ + hb + j * 8 + tg * 2] = o0;
        float2 o1 = { outac[j][2] * i1, outac[j][3] * i1 };
        *(float2*)&ctx[(size_t)(nrow + 8) * D_ + hb + j * 8 + tg * 2] = o1;
    }
}

// ---------------- layer norm (torch semantics: ddof=1, eps on std) ----------------
__global__ void layernorm_kernel(const float* __restrict__ x, const float* __restrict__ alpha,
                                 const float* __restrict__ beta, float* __restrict__ out)
{
    const int row = blockIdx.x;
    const int t = threadIdx.x;
    const float4* xr = (const float4*)(x + (size_t)row * D_);
    float4 v = xr[t];
    float sum = v.x + v.y + v.z + v.w;
    float sq  = v.x * v.x + v.y * v.y + v.z * v.z + v.w * v.w;

    __shared__ float ssum[8], ssq[8];
#pragma unroll
    for (int off = 16; off; off >>= 1) {
        sum += __shfl_xor_sync(0xffffffffu, sum, off);
        sq  += __shfl_xor_sync(0xffffffffu, sq, off);
    }
    int warp = t >> 5, lane = t & 31;
    if (lane == 0) { ssum[warp] = sum; ssq[warp] = sq; }
    __syncthreads();
    float tsum = 0.f, tsq = 0.f;
#pragma unroll
    for (int w = 0; w < 8; w++) { tsum += ssum[w]; tsq += ssq[w]; }

    float mean = tsum * (1.f / D_);
    float var  = (tsq - (float)D_ * mean * mean) * (1.f / (D_ - 1));
    float std_ = sqrtf(fmaxf(var, 0.f));
    float inv  = 1.f / (std_ + EPS_);

    const float4* av = (const float4*)alpha;
    const float4* bv = (const float4*)beta;
    float4 a = av[t], bb = bv[t];
    float4 o;
    o.x = a.x * (v.x - mean) * inv + bb.x;
    o.y = a.y * (v.y - mean) * inv + bb.y;
    o.z = a.z * (v.z - mean) * inv + bb.z;
    o.w = a.w * (v.w - mean) * inv + bb.w;
    ((float4*)(out + (size_t)row * D_))[t] = o;
}

// ---------------- launch ----------------
extern "C" void kernel_launch(void* const* d_in, const int* in_sizes, int n_in,
                              void* d_out, int out_size)
{
    const float* src = (const float*)d_in[0];
    const int*   mask = (const int*)d_in[1];
    const float* Wq = (const float*)d_in[2];
    const float* bq = (const float*)d_in[3];
    const float* Wk = (const float*)d_in[4];
    const float* bk = (const float*)d_in[5];
    const float* Wv = (const float*)d_in[6];
    const float* bv = (const float*)d_in[7];
    const float* Wo = (const float*)d_in[8];
    const float* bo = (const float*)d_in[9];
    const float* W1 = (const float*)d_in[10];
    const float* b1 = (const float*)d_in[11];
    const float* W2 = (const float*)d_in[12];
    const float* b2 = (const float*)d_in[13];
    const float* a1 = (const float*)d_in[14];
    const float* be1 = (const float*)d_in[15];
    const float* a2 = (const float*)d_in[16];
    const float* be2 = (const float*)d_in[17];
    float* out = (float*)d_out;

    void *pq, *pk, *pv, *pctx, *px0, *px1, *pff, *pmf;
    cudaGetSymbolAddress(&pq, g_q);
    cudaGetSymbolAddress(&pk, g_k);
    cudaGetSymbolAddress(&pv, g_v);
    cudaGetSymbolAddress(&pctx, g_ctx);
    cudaGetSymbolAddress(&px0, g_x0);
    cudaGetSymbolAddress(&px1, g_x1);
    cudaGetSymbolAddress(&pff, g_ff);
    cudaGetSymbolAddress(&pmf, g_mflags);

    cudaFuncSetAttribute(flash_tf32, cudaFuncAttributeMaxDynamicSharedMemorySize, FA_SMEM);
    cudaFuncSetAttribute(gemm_tf32, cudaFuncAttributeMaxDynamicSharedMemorySize, GEMM_SMEM);
    cudaFuncSetAttribute(gemm_qkv, cudaFuncAttributeMaxDynamicSharedMemorySize, GEMM_SMEM);

    dim3 blk(256);
    dim3 gD(D_ / 128, N_ / 128);         // (8, 32)
    dim3 gQKV(D_ / 128, N_ / 128, 3);    // (8, 32, 3) — fused QKV
    dim3 gFF(FF_ / 128, N_ / 128);       // (16, 32)

    // mask flags (independent of QKV; tiny)
    maskflags_kernel<<<(N_ * 32 + 255) / 256, blk>>>(mask, (uint32_t*)pmf);

    // fused QKV projections, stored directly in [B,H,S,Dh] layout
    gemm_qkv<<<gQKV, blk, GEMM_SMEM>>>(src, Wq, Wk, Wv, bq, bk, bv,
                                       (float*)pq, (float*)pk, (float*)pv);

    // attention -> ctx in [N, D] layout
    flash_tf32<<<dim3(S_ / 128, B_ * H_), dim3(256), FA_SMEM>>>(
        (const float*)pq, (const float*)pk, (const float*)pv, mask,
        (const uint32_t*)pmf, (float*)pctx);

    // output projection + residual(src)
    gemm_tf32<<<gD, blk, GEMM_SMEM>>>((const float*)pctx, Wo, bo, src, (float*)px0, N_, D_, D_, 0);

    // norm1
    layernorm_kernel<<<N_, blk>>>((const float*)px0, a1, be1, (float*)px1);

    // FFN
    gemm_tf32<<<gFF, blk, GEMM_SMEM>>>((const float*)px1, W1, b1, nullptr, (float*)pff, N_, FF_, D_, FLAG_RELU);
    gemm_tf32<<<gD, blk, GEMM_SMEM>>>((const float*)pff, W2, b2, (const float*)px1, (float*)px0, N_, D_, FF_, 0);

    // norm2 -> out
    layernorm_kernel<<<N_, blk>>>((const float*)px0, a2, be2, out);
}

// round 15
// speedup vs baseline: 1.0824x; 1.0824x over previous
#include <cuda_runtime.h>
#include <cuda_bf16.h>
#include <cstdint>

#define B_   2
#define S_   2048
#define D_   1024
#define H_   16
#define DH_  64
#define FF_  2048
#define N_   (B_*S_)     // 4096
#define EPS_ 1e-6f

#define FLAG_RELU 1

// ---------------- scratch (allocation-free) ----------------
__device__ float g_q[N_ * D_];     // [B,H,S,Dh]
__device__ float g_k[N_ * D_];
__device__ float g_v[N_ * D_];
__device__ float g_ctx[N_ * D_];   // [N, D]
__device__ float g_x0[N_ * D_];
__device__ float g_x1[N_ * D_];
__device__ float g_ff[N_ * FF_];
__device__ uint32_t g_mflags[N_];  // [b*S + qrow] -> bit per 64-key tile: 1 = all nonzero

// ---------------- helpers ----------------
__device__ __forceinline__ uint32_t f2tf32(float x) {
    uint32_t r;
    asm("cvt.rna.tf32.f32 %0, %1;" : "=r"(r) : "f"(x));
    return r;
}

__device__ __forceinline__ uint32_t pack_bf16(float lo, float hi) {
    uint32_t r;
    asm("cvt.rn.bf16x2.f32 %0, %1, %2;" : "=r"(r) : "f"(hi), "f"(lo));
    return r;
}

__device__ __forceinline__ void mma_tf32(float c[4], uint32_t a0, uint32_t a1, uint32_t a2, uint32_t a3,
                                         uint32_t b0, uint32_t b1) {
    asm volatile("mma.sync.aligned.m16n8k8.row.col.f32.tf32.tf32.f32 "
                 "{%0,%1,%2,%3}, {%4,%5,%6,%7}, {%8,%9}, {%0,%1,%2,%3};"
                 : "+f"(c[0]), "+f"(c[1]), "+f"(c[2]), "+f"(c[3])
                 : "r"(a0), "r"(a1), "r"(a2), "r"(a3), "r"(b0), "r"(b1));
}

__device__ __forceinline__ void mma_bf16(float c[4], uint32_t a0, uint32_t a1, uint32_t a2, uint32_t a3,
                                         uint32_t b0, uint32_t b1) {
    asm volatile("mma.sync.aligned.m16n8k16.row.col.f32.bf16.bf16.f32 "
                 "{%0,%1,%2,%3}, {%4,%5,%6,%7}, {%8,%9}, {%0,%1,%2,%3};"
                 : "+f"(c[0]), "+f"(c[1]), "+f"(c[2]), "+f"(c[3])
                 : "r"(a0), "r"(a1), "r"(a2), "r"(a3), "r"(b0), "r"(b1));
}

__device__ __forceinline__ void cp_async16(uint32_t dst, const void* src) {
    asm volatile("cp.async.cg.shared.global [%0], [%1], 16;" :: "r"(dst), "l"(src));
}
__device__ __forceinline__ void cp_commit() { asm volatile("cp.async.commit_group;" ::: "memory"); }
__device__ __forceinline__ void cp_wait1()  { asm volatile("cp.async.wait_group 1;" ::: "memory"); }
__device__ __forceinline__ void cp_wait0()  { asm volatile("cp.async.wait_group 0;" ::: "memory"); }

// fast exp on the FMA pipe (no MUFU)
__device__ __forceinline__ float fast_exp(float x) {
    float y = fmaxf(x * 1.4426950408889634f, -126.0f);
    float t = y + 12582912.0f;
    int   n = __float_as_int(t) - 0x4B400000;
    float f = y - (t - 12582912.0f);
    float p = 1.3333558146e-3f;
    p = fmaf(p, f, 9.6181291e-3f);
    p = fmaf(p, f, 5.5504108664e-2f);
    p = fmaf(p, f, 2.4022650696e-1f);
    p = fmaf(p, f, 6.9314718056e-1f);
    p = fmaf(p, f, 1.0f);
    return p * __int_as_float((n + 127) << 23);
}

// ---------------- mask flags precompute: one warp per (b,row) ----------------
__global__ void maskflags_kernel(const int* __restrict__ mask, uint32_t* __restrict__ flags)
{
    const int gw = (blockIdx.x * blockDim.x + threadIdx.x) >> 5;   // row index 0..N_-1
    const int lane = threadIdx.x & 31;
    if (gw >= N_) return;
    const int* row = mask + (size_t)gw * S_;
    uint32_t bits = 0;
#pragma unroll
    for (int kt = 0; kt < 32; kt++) {
        int2 v = *(const int2*)&row[kt * 64 + lane * 2];
        int nz = (v.x != 0) & (v.y != 0);
        nz = __all_sync(0xffffffffu, nz);
        bits |= (uint32_t)nz << kt;
    }
    if (lane == 0) flags[gw] = bits;
}

// ---------------- GEMM: BK=16, 3-stage cp.async (r12 proven), conflict-free LDS.64 ----------------
// pitch 24 words: pair-bank m = 12g+tg mod 16, all distinct per phase.
// k-slot permutation: slot tg <- k=2tg, slot tg+4 <- k=2tg+1 (A and B identical -> exact)
// Prefetch for kt+2 issued right after the barrier (before mma) for max overlap depth.
#define GPITCH 24
#define GSTAGES 3
#define GSTAGE_U32 (128 * GPITCH)
#define GEMM_SMEM (GSTAGES * 2 * GSTAGE_U32 * 4)   // 73728 B

struct GemmCtx {
    int t, wm, wn, g, tg, lrr, kq;
};

__device__ __forceinline__ void gemm_mainloop(
    const float* Aptr0, const float* Aptr1, const float* Wptr0, const float* Wptr1,
    uint32_t* Asm, uint32_t* Wsm, const GemmCtx& cx, int K, float acc[4][4][4])
{
    const uint32_t aBase = (uint32_t)__cvta_generic_to_shared(Asm);
    const uint32_t wBase = (uint32_t)__cvta_generic_to_shared(Wsm);
    const uint32_t off0 = (cx.lrr * GPITCH + cx.kq * 4) * 4;
    const uint32_t off1 = ((cx.lrr + 64) * GPITCH + cx.kq * 4) * 4;
    const int KT = K >> 4;

#pragma unroll
    for (int st = 0; st < GSTAGES - 1; st++) {
        const uint32_t sb = st * GSTAGE_U32 * 4;
        const int k0 = st * 16;
        cp_async16(aBase + sb + off0, Aptr0 + k0);
        cp_async16(aBase + sb + off1, Aptr1 + k0);
        cp_async16(wBase + sb + off0, Wptr0 + k0);
        cp_async16(wBase + sb + off1, Wptr1 + k0);
        cp_commit();
    }

    for (int kt = 0; kt < KT; kt++) {
        cp_wait1();
        __syncthreads();
        const uint32_t* As_ = Asm + (kt % GSTAGES) * GSTAGE_U32;
        const uint32_t* Ws_ = Wsm + (kt % GSTAGES) * GSTAGE_U32;

        // prefetch kt+2 immediately (target buffer = (kt-1)%3, readers done at barrier)
        const int nk = kt + GSTAGES - 1;
        if (nk < KT) {
            const uint32_t sb = (nk % GSTAGES) * GSTAGE_U32 * 4;
            const int k0 = nk * 16;
            cp_async16(aBase + sb + off0, Aptr0 + k0);
            cp_async16(aBase + sb + off1, Aptr1 + k0);
            cp_async16(wBase + sb + off0, Wptr0 + k0);
            cp_async16(wBase + sb + off1, Wptr1 + k0);
        }
        cp_commit();   // uniform group count for wait_group 1

#pragma unroll
        for (int ks = 0; ks < 2; ks++) {
            const int kb = ks * 8 + 2 * cx.tg;
            uint2 alo[4], ahi[4], bfp[4];
#pragma unroll
            for (int mi = 0; mi < 4; mi++) {
                const int nb = cx.wm * 64 + mi * 16;
                alo[mi] = *(const uint2*)&As_[(nb + cx.g) * GPITCH + kb];
                ahi[mi] = *(const uint2*)&As_[(nb + cx.g + 8) * GPITCH + kb];
            }
#pragma unroll
            for (int ni = 0; ni < 4; ni++) {
                const int mb = cx.wn * 32 + ni * 8;
                bfp[ni] = *(const uint2*)&Ws_[(mb + cx.g) * GPITCH + kb];
            }
#pragma unroll
            for (int mi = 0; mi < 4; mi++)
#pragma unroll
                for (int ni = 0; ni < 4; ni++)
                    mma_tf32(acc[mi][ni], alo[mi].x, ahi[mi].x, alo[mi].y, ahi[mi].y,
                             bfp[ni].x, bfp[ni].y);
        }
    }
    __syncthreads();
}

__device__ __forceinline__ GemmCtx make_ctx(int t) {
    GemmCtx cx;
    cx.t = t;
    int w = t >> 5;
    cx.wm = w >> 2;
    cx.wn = w & 3;
    int lane = t & 31;
    cx.g  = lane >> 2;
    cx.tg = lane & 3;
    cx.lrr = t >> 2;
    cx.kq  = t & 3;
    return cx;
}

// ---------------- generic GEMM (Wo, FF1, FF2) ----------------
__global__ __launch_bounds__(256, 2)
void gemm_tf32(const float* __restrict__ A, const float* __restrict__ W,
               const float* __restrict__ bias, const float* __restrict__ residual,
               float* __restrict__ C, int N, int M, int K, int flags)
{
    extern __shared__ uint32_t gsm[];
    uint32_t* Asm = gsm;
    uint32_t* Wsm = gsm + GSTAGES * GSTAGE_U32;

    GemmCtx cx = make_ctx(threadIdx.x);
    const int n0 = blockIdx.y * 128, m0 = blockIdx.x * 128;

    float acc[4][4][4];
#pragma unroll
    for (int mi = 0; mi < 4; mi++)
#pragma unroll
        for (int ni = 0; ni < 4; ni++)
#pragma unroll
            for (int c = 0; c < 4; c++) acc[mi][ni][c] = 0.f;

    gemm_mainloop(A + (size_t)(n0 + cx.lrr) * K + cx.kq * 4,
                  A + (size_t)(n0 + cx.lrr + 64) * K + cx.kq * 4,
                  W + (size_t)(m0 + cx.lrr) * K + cx.kq * 4,
                  W + (size_t)(m0 + cx.lrr + 64) * K + cx.kq * 4,
                  Asm, Wsm, cx, K, acc);

#pragma unroll
    for (int mi = 0; mi < 4; mi++) {
#pragma unroll
        for (int ni = 0; ni < 4; ni++) {
#pragma unroll
            for (int c = 0; c < 4; c++) {
                int n = n0 + cx.wm * 64 + mi * 16 + cx.g + ((c >> 1) ? 8 : 0);
                int m = m0 + cx.wn * 32 + ni * 8 + cx.tg * 2 + (c & 1);
                float v = acc[mi][ni][c] + bias[m];
                if (residual) v += residual[(size_t)n * M + m];
                if (flags & FLAG_RELU) v = fmaxf(v, 0.f);
                C[(size_t)n * M + m] = v;
            }
        }
    }
}

// ---------------- fused QKV GEMM: gridDim.z = 3 selects projection ----------------
__global__ __launch_bounds__(256, 2)
void gemm_qkv(const float* __restrict__ A,
              const float* __restrict__ Wq, const float* __restrict__ Wk, const float* __restrict__ Wv,
              const float* __restrict__ bq, const float* __restrict__ bk, const float* __restrict__ bv,
              float* __restrict__ Cq, float* __restrict__ Ck, float* __restrict__ Cv)
{
    extern __shared__ uint32_t gsm[];
    uint32_t* Asm = gsm;
    uint32_t* Wsm = gsm + GSTAGES * GSTAGE_U32;

    const int z = blockIdx.z;
    const float* W    = (z == 0) ? Wq : (z == 1) ? Wk : Wv;
    const float* bias = (z == 0) ? bq : (z == 1) ? bk : bv;
    float* C          = (z == 0) ? Cq : (z == 1) ? Ck : Cv;

    GemmCtx cx = make_ctx(threadIdx.x);
    const int n0 = blockIdx.y * 128, m0 = blockIdx.x * 128;
    const int K = D_;

    float acc[4][4][4];
#pragma unroll
    for (int mi = 0; mi < 4; mi++)
#pragma unroll
        for (int ni = 0; ni < 4; ni++)
#pragma unroll
            for (int c = 0; c < 4; c++) acc[mi][ni][c] = 0.f;

    gemm_mainloop(A + (size_t)(n0 + cx.lrr) * K + cx.kq * 4,
                  A + (size_t)(n0 + cx.lrr + 64) * K + cx.kq * 4,
                  W + (size_t)(m0 + cx.lrr) * K + cx.kq * 4,
                  W + (size_t)(m0 + cx.lrr + 64) * K + cx.kq * 4,
                  Asm, Wsm, cx, K, acc);

    // epilogue with head-layout scatter: [B,H,S,Dh]
#pragma unroll
    for (int mi = 0; mi < 4; mi++) {
#pragma unroll
        for (int ni = 0; ni < 4; ni++) {
#pragma unroll
            for (int c = 0; c < 4; c++) {
                int n = n0 + cx.wm * 64 + mi * 16 + cx.g + ((c >> 1) ? 8 : 0);
                int m = m0 + cx.wn * 32 + ni * 8 + cx.tg * 2 + (c & 1);
                float v = acc[mi][ni][c] + bias[m];
                int b = n >> 11, s = n & 2047;
                int h = m >> 6,  dh = m & 63;
                C[(((size_t)(b * H_ + h)) * S_ + s) * DH_ + dh] = v;
            }
        }
    }
}

// ---------------- flash attention: double-buffered K/V + flag-gated mask (r12 proven) ----------------
#define FAP 72
#define VPP 36
#define KBUF_U32 (64 * FAP)
#define VBUF_U32 (64 * VPP)
#define FA_SMEM ((128 * FAP + 2 * KBUF_U32 + 2 * VBUF_U32) * 4)   // 92160 B

__global__ __launch_bounds__(256, 2)
void flash_tf32(const float* __restrict__ q, const float* __restrict__ k,
                const float* __restrict__ v, const int* __restrict__ mask,
                const uint32_t* __restrict__ mflags, float* __restrict__ ctx)
{
    extern __shared__ uint32_t sm4[];
    uint32_t* Qs   = sm4;                            // [128 q][d] tf32
    uint32_t* Ks   = sm4 + 128 * FAP;                // [2][64 kc][d] raw f32
    uint32_t* VsTb = sm4 + 128 * FAP + 2 * KBUF_U32; // [2][64 d][32 kp] bf16x2

    const int t = threadIdx.x;
    const int w = t >> 5, lane = t & 31;
    const int g = lane >> 2, tg = lane & 3;
    const int qb = w * 16;
    const int bh = blockIdx.y, b = bh >> 4, h = bh & 15;
    const int q0 = blockIdx.x * 128;
    const float* qh = q + (size_t)bh * S_ * DH_;
    const float* kh = k + (size_t)bh * S_ * DH_;
    const float* vh = v + (size_t)bh * S_ * DH_;
    const int* maskb = mask + (size_t)b * S_ * S_;

    const uint32_t ksBase = (uint32_t)__cvta_generic_to_shared(Ks);

    const int krow = t & 63;            // K loader: row, 4 threads/row
    const int kcol = (t >> 6) * 16;
    const int kp = t & 31;              // V loader: keypair
    const int db = (t >> 5) * 8;

    const uint32_t bits0 = mflags[b * S_ + q0 + qb + g];
    const uint32_t bits1 = mflags[b * S_ + q0 + qb + g + 8];

    {   // Q tile (128x64) -> smem tf32 (rna-rounded, loaded once)
        const int lr = t >> 1, lc = (t & 1) * 32;
        const float4* src4 = (const float4*)(qh + (size_t)(q0 + lr) * 64 + lc);
#pragma unroll
        for (int i = 0; i < 8; i++) {
            float4 a = src4[i];
            uint4 u = { f2tf32(a.x), f2tf32(a.y), f2tf32(a.z), f2tf32(a.w) };
            *(uint4*)&Qs[lr * FAP + lc + i * 4] = u;
        }
    }

    // prologue: tile 0 into buffer 0
    {
        const float* ksrc = kh + (size_t)krow * 64 + kcol;
        const uint32_t kdst = ksBase + (krow * FAP + kcol) * 4;
#pragma unroll
        for (int i = 0; i < 4; i++) cp_async16(kdst + i * 16, ksrc + i * 4);
        cp_commit();
        const float4* v0p = (const float4*)(vh + (size_t)(2 * kp) * 64 + db);
        const float4* v1p = (const float4*)(vh + (size_t)(2 * kp + 1) * 64 + db);
        float4 e0 = v0p[0], e1 = v0p[1], o0 = v1p[0], o1 = v1p[1];
        uint32_t* Vb = VsTb;
        Vb[(db + 0) * VPP + kp] = pack_bf16(e0.x, o0.x);
        Vb[(db + 1) * VPP + kp] = pack_bf16(e0.y, o0.y);
        Vb[(db + 2) * VPP + kp] = pack_bf16(e0.z, o0.z);
        Vb[(db + 3) * VPP + kp] = pack_bf16(e0.w, o0.w);
        Vb[(db + 4) * VPP + kp] = pack_bf16(e1.x, o1.x);
        Vb[(db + 5) * VPP + kp] = pack_bf16(e1.y, o1.y);
        Vb[(db + 6) * VPP + kp] = pack_bf16(e1.z, o1.z);
        Vb[(db + 7) * VPP + kp] = pack_bf16(e1.w, o1.w);
        cp_wait0();
    }
    __syncthreads();

    float outac[8][4];
#pragma unroll
    for (int j = 0; j < 8; j++)
#pragma unroll
        for (int c = 0; c < 4; c++) outac[j][c] = 0.f;
    float mrow0 = -1e30f, mrow1 = -1e30f;
    float lrow0 = 0.f, lrow1 = 0.f;

    const int NT = S_ / 64;   // 32
    for (int it = 0; it < NT; it++) {
        const int buf = it & 1;
        const uint32_t* Kb = Ks + buf * KBUF_U32;
        const uint32_t* Vb = VsTb + buf * VBUF_U32;
        const bool more = (it + 1 < NT);

        float4 e0, e1, o0, o1;
        if (more) {
            const int kn = (it + 1) * 64;
            const float* ksrc = kh + (size_t)(kn + krow) * 64 + kcol;
            const uint32_t kdst = ksBase + ((buf ^ 1) * KBUF_U32 + krow * FAP + kcol) * 4;
#pragma unroll
            for (int i = 0; i < 4; i++) cp_async16(kdst + i * 16, ksrc + i * 4);
            cp_commit();
            const float4* v0p = (const float4*)(vh + (size_t)(kn + 2 * kp) * 64 + db);
            const float4* v1p = (const float4*)(vh + (size_t)(kn + 2 * kp + 1) * 64 + db);
            e0 = v0p[0]; e1 = v0p[1]; o0 = v1p[0]; o1 = v1p[1];
        }

        // S = Q K^T  (tf32; conflict-free LDS.64 fragments, k-slot permuted)
        float sa[8][4];
#pragma unroll
        for (int j = 0; j < 8; j++)
#pragma unroll
            for (int c = 0; c < 4; c++) sa[j][c] = 0.f;
#pragma unroll
        for (int kc = 0; kc < 8; kc++) {
            const int kb = kc * 8 + 2 * tg;
            uint2 qlo = *(const uint2*)&Qs[(qb + g) * FAP + kb];
            uint2 qhi = *(const uint2*)&Qs[(qb + g + 8) * FAP + kb];
#pragma unroll
            for (int j = 0; j < 8; j++) {
                uint2 kf = *(const uint2*)&Kb[(j * 8 + g) * FAP + kb];
                mma_tf32(sa[j], qlo.x, qhi.x, qlo.y, qhi.y, kf.x, kf.y);
            }
        }

        if (more) {
            uint32_t* Vn = VsTb + (buf ^ 1) * VBUF_U32;
            Vn[(db + 0) * VPP + kp] = pack_bf16(e0.x, o0.x);
            Vn[(db + 1) * VPP + kp] = pack_bf16(e0.y, o0.y);
            Vn[(db + 2) * VPP + kp] = pack_bf16(e0.z, o0.z);
            Vn[(db + 3) * VPP + kp] = pack_bf16(e0.w, o0.w);
            Vn[(db + 4) * VPP + kp] = pack_bf16(e1.x, o1.x);
            Vn[(db + 5) * VPP + kp] = pack_bf16(e1.y, o1.y);
            Vn[(db + 6) * VPP + kp] = pack_bf16(e1.z, o1.z);
            Vn[(db + 7) * VPP + kp] = pack_bf16(e1.w, o1.w);
        }

        // scale + mask (flag-gated)
        const bool allok = (((bits0 >> it) & (bits1 >> it)) & 1u) != 0u;
        if (allok) {
#pragma unroll
            for (int j = 0; j < 8; j++) {
                sa[j][0] *= 0.125f; sa[j][1] *= 0.125f;
                sa[j][2] *= 0.125f; sa[j][3] *= 0.125f;
            }
        } else {
            const int k0 = it * 64;
            const size_t mrow_a = (size_t)(q0 + qb + g) * S_ + k0;
            const size_t mrow_b = (size_t)(q0 + qb + g + 8) * S_ + k0;
#pragma unroll
            for (int j = 0; j < 8; j++) {
                int col = j * 8 + tg * 2;
                int2 m0 = *(const int2*)&maskb[mrow_a + col];
                int2 m1 = *(const int2*)&maskb[mrow_b + col];
                sa[j][0] = m0.x ? sa[j][0] * 0.125f : -1e9f;
                sa[j][1] = m0.y ? sa[j][1] * 0.125f : -1e9f;
                sa[j][2] = m1.x ? sa[j][2] * 0.125f : -1e9f;
                sa[j][3] = m1.y ? sa[j][3] * 0.125f : -1e9f;
            }
        }

        // online softmax (rows g, g+8), quad reduce
        float mx0 = -1e30f, mx1 = -1e30f;
#pragma unroll
        for (int j = 0; j < 8; j++) {
            mx0 = fmaxf(mx0, fmaxf(sa[j][0], sa[j][1]));
            mx1 = fmaxf(mx1, fmaxf(sa[j][2], sa[j][3]));
        }
        mx0 = fmaxf(mx0, __shfl_xor_sync(0xffffffffu, mx0, 1));
        mx0 = fmaxf(mx0, __shfl_xor_sync(0xffffffffu, mx0, 2));
        mx1 = fmaxf(mx1, __shfl_xor_sync(0xffffffffu, mx1, 1));
        mx1 = fmaxf(mx1, __shfl_xor_sync(0xffffffffu, mx1, 2));

        float mn0 = fmaxf(mrow0, mx0), mn1 = fmaxf(mrow1, mx1);
        float cr0 = fast_exp(mrow0 - mn0), cr1 = fast_exp(mrow1 - mn1);
        mrow0 = mn0; mrow1 = mn1;

        float rs0 = 0.f, rs1 = 0.f;
#pragma unroll
        for (int j = 0; j < 8; j++) {
            sa[j][0] = fast_exp(sa[j][0] - mn0);
            sa[j][1] = fast_exp(sa[j][1] - mn0);
            sa[j][2] = fast_exp(sa[j][2] - mn1);
            sa[j][3] = fast_exp(sa[j][3] - mn1);
            rs0 += sa[j][0] + sa[j][1];
            rs1 += sa[j][2] + sa[j][3];
        }
        rs0 += __shfl_xor_sync(0xffffffffu, rs0, 1);
        rs0 += __shfl_xor_sync(0xffffffffu, rs0, 2);
        rs1 += __shfl_xor_sync(0xffffffffu, rs1, 1);
        rs1 += __shfl_xor_sync(0xffffffffu, rs1, 2);
        lrow0 = lrow0 * cr0 + rs0;
        lrow1 = lrow1 * cr1 + rs1;

#pragma unroll
        for (int j = 0; j < 8; j++) {
            outac[j][0] *= cr0; outac[j][1] *= cr0;
            outac[j][2] *= cr1; outac[j][3] *= cr1;
        }

        // out += P V  — P packed from registers (bf16), V from current buffer
#pragma unroll
        for (int s = 0; s < 4; s++) {
            uint32_t a0 = pack_bf16(sa[2*s][0],   sa[2*s][1]);
            uint32_t a1 = pack_bf16(sa[2*s][2],   sa[2*s][3]);
            uint32_t a2 = pack_bf16(sa[2*s+1][0], sa[2*s+1][1]);
            uint32_t a3 = pack_bf16(sa[2*s+1][2], sa[2*s+1][3]);
            const int kpb = 8 * s;
#pragma unroll
            for (int j = 0; j < 8; j++) {
                uint32_t b0 = Vb[(j * 8 + g) * VPP + kpb + tg];
                uint32_t b1 = Vb[(j * 8 + g) * VPP + kpb + tg + 4];
                mma_bf16(outac[j], a0, a1, a2, a3, b0, b1);
            }
        }

        if (more) cp_wait0();
        __syncthreads();
    }

    // epilogue
    float i0 = 1.f / lrow0, i1 = 1.f / lrow1;
    const int nrow = b * S_ + q0 + qb + g;
    const int hb = h * 64;
#pragma unroll
    for (int j = 0; j < 8; j++) {
        float2 o0 = { outac[j][0] * i0, outac[j][1] * i0 };
        *(float2*)&ctx[(size_t)nrow * D_ + hb + j * 8 + tg * 2] = o0;
        float2 o1 = { outac[j][2] * i1, outac[j][3] * i1 };
        *(float2*)&ctx[(size_t)(nrow + 8) * D_ + hb + j * 8 + tg * 2] = o1;
    }
}

// ---------------- layer norm (torch semantics: ddof=1, eps on std) ----------------
__global__ void layernorm_kernel(const float* __restrict__ x, const float* __restrict__ alpha,
                                 const float* __restrict__ beta, float* __restrict__ out)
{
    const int row = blockIdx.x;
    const int t = threadIdx.x;
    const float4* xr = (const float4*)(x + (size_t)row * D_);
    float4 v = xr[t];
    float sum = v.x + v.y + v.z + v.w;
    float sq  = v.x * v.x + v.y * v.y + v.z * v.z + v.w * v.w;

    __shared__ float ssum[8], ssq[8];
#pragma unroll
    for (int off = 16; off; off >>= 1) {
        sum += __shfl_xor_sync(0xffffffffu, sum, off);
        sq  += __shfl_xor_sync(0xffffffffu, sq, off);
    }
    int warp = t >> 5, lane = t & 31;
    if (lane == 0) { ssum[warp] = sum; ssq[warp] = sq; }
    __syncthreads();
    float tsum = 0.f, tsq = 0.f;
#pragma unroll
    for (int w = 0; w < 8; w++) { tsum += ssum[w]; tsq += ssq[w]; }

    float mean = tsum * (1.f / D_);
    float var  = (tsq - (float)D_ * mean * mean) * (1.f / (D_ - 1));
    float std_ = sqrtf(fmaxf(var, 0.f));
    float inv  = 1.f / (std_ + EPS_);

    const float4* av = (const float4*)alpha;
    const float4* bv = (const float4*)beta;
    float4 a = av[t], bb = bv[t];
    float4 o;
    o.x = a.x * (v.x - mean) * inv + bb.x;
    o.y = a.y * (v.y - mean) * inv + bb.y;
    o.z = a.z * (v.z - mean) * inv + bb.z;
    o.w = a.w * (v.w - mean) * inv + bb.w;
    ((float4*)(out + (size_t)row * D_))[t] = o;
}

// ---------------- launch ----------------
extern "C" void kernel_launch(void* const* d_in, const int* in_sizes, int n_in,
                              void* d_out, int out_size)
{
    const float* src = (const float*)d_in[0];
    const int*   mask = (const int*)d_in[1];
    const float* Wq = (const float*)d_in[2];
    const float* bq = (const float*)d_in[3];
    const float* Wk = (const float*)d_in[4];
    const float* bk = (const float*)d_in[5];
    const float* Wv = (const float*)d_in[6];
    const float* bv = (const float*)d_in[7];
    const float* Wo = (const float*)d_in[8];
    const float* bo = (const float*)d_in[9];
    const float* W1 = (const float*)d_in[10];
    const float* b1 = (const float*)d_in[11];
    const float* W2 = (const float*)d_in[12];
    const float* b2 = (const float*)d_in[13];
    const float* a1 = (const float*)d_in[14];
    const float* be1 = (const float*)d_in[15];
    const float* a2 = (const float*)d_in[16];
    const float* be2 = (const float*)d_in[17];
    float* out = (float*)d_out;

    void *pq, *pk, *pv, *pctx, *px0, *px1, *pff, *pmf;
    cudaGetSymbolAddress(&pq, g_q);
    cudaGetSymbolAddress(&pk, g_k);
    cudaGetSymbolAddress(&pv, g_v);
    cudaGetSymbolAddress(&pctx, g_ctx);
    cudaGetSymbolAddress(&px0, g_x0);
    cudaGetSymbolAddress(&px1, g_x1);
    cudaGetSymbolAddress(&pff, g_ff);
    cudaGetSymbolAddress(&pmf, g_mflags);

    cudaFuncSetAttribute(flash_tf32, cudaFuncAttributeMaxDynamicSharedMemorySize, FA_SMEM);
    cudaFuncSetAttribute(gemm_tf32, cudaFuncAttributeMaxDynamicSharedMemorySize, GEMM_SMEM);
    cudaFuncSetAttribute(gemm_qkv, cudaFuncAttributeMaxDynamicSharedMemorySize, GEMM_SMEM);

    dim3 blk(256);
    dim3 gD(D_ / 128, N_ / 128);         // (8, 32)
    dim3 gQKV(D_ / 128, N_ / 128, 3);    // (8, 32, 3) — fused QKV
    dim3 gFF(FF_ / 128, N_ / 128);       // (16, 32)

    // mask flags (independent of QKV; tiny)
    maskflags_kernel<<<(N_ * 32 + 255) / 256, blk>>>(mask, (uint32_t*)pmf);

    // fused QKV projections, stored directly in [B,H,S,Dh] layout
    gemm_qkv<<<gQKV, blk, GEMM_SMEM>>>(src, Wq, Wk, Wv, bq, bk, bv,
                                       (float*)pq, (float*)pk, (float*)pv);

    // attention -> ctx in [N, D] layout
    flash_tf32<<<dim3(S_ / 128, B_ * H_), dim3(256), FA_SMEM>>>(
        (const float*)pq, (const float*)pk, (const float*)pv, mask,
        (const uint32_t*)pmf, (float*)pctx);

    // output projection + residual(src)
    gemm_tf32<<<gD, blk, GEMM_SMEM>>>((const float*)pctx, Wo, bo, src, (float*)px0, N_, D_, D_, 0);

    // norm1
    layernorm_kernel<<<N_, blk>>>((const float*)px0, a1, be1, (float*)px1);

    // FFN
    gemm_tf32<<<gFF, blk, GEMM_SMEM>>>((const float*)px1, W1, b1, nullptr, (float*)pff, N_, FF_, D_, FLAG_RELU);
    gemm_tf32<<<gD, blk, GEMM_SMEM>>>((const float*)pff, W2, b2, (const float*)px1, (float*)px0, N_, D_, FF_, 0);

    // norm2 -> out
    layernorm_kernel<<<N_, blk>>>((const float*)px0, a2, be2, out);
}

// round 16
// speedup vs baseline: 1.1678x; 1.0789x over previous
#include <cuda_runtime.h>
#include <cuda_bf16.h>
#include <cstdint>

#define B_   2
#define S_   2048
#define D_   1024
#define H_   16
#define DH_  64
#define FF_  2048
#define N_   (B_*S_)     // 4096
#define EPS_ 1e-6f

#define FLAG_RELU 1

// ---------------- scratch (allocation-free) ----------------
__device__ float g_q[N_ * D_];     // [B,H,S,Dh]
__device__ float g_k[N_ * D_];
__device__ float g_v[N_ * D_];
__device__ float g_ctx[N_ * D_];   // [N, D]
__device__ float g_x0[N_ * D_];
__device__ float g_x1[N_ * D_];
__device__ float g_ff[N_ * FF_];
__device__ uint32_t g_mflags[N_];  // [b*S + qrow] -> bit per 64-key tile: 1 = all nonzero

// ---------------- helpers ----------------
__device__ __forceinline__ uint32_t f2tf32(float x) {
    uint32_t r;
    asm("cvt.rna.tf32.f32 %0, %1;" : "=r"(r) : "f"(x));
    return r;
}

__device__ __forceinline__ uint32_t pack_bf16(float lo, float hi) {
    uint32_t r;
    asm("cvt.rn.bf16x2.f32 %0, %1, %2;" : "=r"(r) : "f"(hi), "f"(lo));
    return r;
}

__device__ __forceinline__ void mma_tf32(float c[4], uint32_t a0, uint32_t a1, uint32_t a2, uint32_t a3,
                                         uint32_t b0, uint32_t b1) {
    asm volatile("mma.sync.aligned.m16n8k8.row.col.f32.tf32.tf32.f32 "
                 "{%0,%1,%2,%3}, {%4,%5,%6,%7}, {%8,%9}, {%0,%1,%2,%3};"
                 : "+f"(c[0]), "+f"(c[1]), "+f"(c[2]), "+f"(c[3])
                 : "r"(a0), "r"(a1), "r"(a2), "r"(a3), "r"(b0), "r"(b1));
}

__device__ __forceinline__ void mma_bf16(float c[4], uint32_t a0, uint32_t a1, uint32_t a2, uint32_t a3,
                                         uint32_t b0, uint32_t b1) {
    asm volatile("mma.sync.aligned.m16n8k16.row.col.f32.bf16.bf16.f32 "
                 "{%0,%1,%2,%3}, {%4,%5,%6,%7}, {%8,%9}, {%0,%1,%2,%3};"
                 : "+f"(c[0]), "+f"(c[1]), "+f"(c[2]), "+f"(c[3])
                 : "r"(a0), "r"(a1), "r"(a2), "r"(a3), "r"(b0), "r"(b1));
}

__device__ __forceinline__ void cp_async16(uint32_t dst, const void* src) {
    asm volatile("cp.async.cg.shared.global [%0], [%1], 16;" :: "r"(dst), "l"(src));
}
__device__ __forceinline__ void cp_commit() { asm volatile("cp.async.commit_group;" ::: "memory"); }
__device__ __forceinline__ void cp_wait1()  { asm volatile("cp.async.wait_group 1;" ::: "memory"); }
__device__ __forceinline__ void cp_wait0()  { asm volatile("cp.async.wait_group 0;" ::: "memory"); }

// fast exp on the FMA pipe (no MUFU)
__device__ __forceinline__ float fast_exp(float x) {
    float y = fmaxf(x * 1.4426950408889634f, -126.0f);
    float t = y + 12582912.0f;
    int   n = __float_as_int(t) - 0x4B400000;
    float f = y - (t - 12582912.0f);
    float p = 1.3333558146e-3f;
    p = fmaf(p, f, 9.6181291e-3f);
    p = fmaf(p, f, 5.5504108664e-2f);
    p = fmaf(p, f, 2.4022650696e-1f);
    p = fmaf(p, f, 6.9314718056e-1f);
    p = fmaf(p, f, 1.0f);
    return p * __int_as_float((n + 127) << 23);
}

// ---------------- mask flags precompute: one warp per (b,row) ----------------
__global__ void maskflags_kernel(const int* __restrict__ mask, uint32_t* __restrict__ flags)
{
    const int gw = (blockIdx.x * blockDim.x + threadIdx.x) >> 5;   // row index 0..N_-1
    const int lane = threadIdx.x & 31;
    if (gw >= N_) return;
    const int* row = mask + (size_t)gw * S_;
    uint32_t bits = 0;
#pragma unroll
    for (int kt = 0; kt < 32; kt++) {
        int2 v = *(const int2*)&row[kt * 64 + lane * 2];
        int nz = (v.x != 0) & (v.y != 0);
        nz = __all_sync(0xffffffffu, nz);
        bits |= (uint32_t)nz << kt;
    }
    if (lane == 0) flags[gw] = bits;
}

// ---------------- GEMM: BK=16, 3-stage cp.async (r12 exact), conflict-free LDS.64 ----------------
// pitch 24 words: pair-bank m = 12g+tg mod 16, all distinct per phase.
// k-slot permutation: slot tg <- k=2tg, slot tg+4 <- k=2tg+1 (A and B identical -> exact)
// Prefetch issued AFTER the mma block (r12 order — r15 showed hoisting it regresses).
#define GPITCH 24
#define GSTAGES 3
#define GSTAGE_U32 (128 * GPITCH)
#define GEMM_SMEM (GSTAGES * 2 * GSTAGE_U32 * 4)   // 73728 B

struct GemmCtx {
    int t, wm, wn, g, tg, lrr, kq;
};

__device__ __forceinline__ void gemm_mainloop(
    const float* Aptr0, const float* Aptr1, const float* Wptr0, const float* Wptr1,
    uint32_t* Asm, uint32_t* Wsm, const GemmCtx& cx, int K, float acc[4][4][4])
{
    const uint32_t aBase = (uint32_t)__cvta_generic_to_shared(Asm);
    const uint32_t wBase = (uint32_t)__cvta_generic_to_shared(Wsm);
    const uint32_t off0 = (cx.lrr * GPITCH + cx.kq * 4) * 4;
    const uint32_t off1 = ((cx.lrr + 64) * GPITCH + cx.kq * 4) * 4;
    const int KT = K >> 4;

#pragma unroll
    for (int st = 0; st < GSTAGES - 1; st++) {
        const uint32_t sb = st * GSTAGE_U32 * 4;
        const int k0 = st * 16;
        cp_async16(aBase + sb + off0, Aptr0 + k0);
        cp_async16(aBase + sb + off1, Aptr1 + k0);
        cp_async16(wBase + sb + off0, Wptr0 + k0);
        cp_async16(wBase + sb + off1, Wptr1 + k0);
        cp_commit();
    }

    for (int kt = 0; kt < KT; kt++) {
        cp_wait1();
        __syncthreads();
        const uint32_t* As_ = Asm + (kt % GSTAGES) * GSTAGE_U32;
        const uint32_t* Ws_ = Wsm + (kt % GSTAGES) * GSTAGE_U32;

#pragma unroll
        for (int ks = 0; ks < 2; ks++) {
            const int kb = ks * 8 + 2 * cx.tg;
            uint2 alo[4], ahi[4], bfp[4];
#pragma unroll
            for (int mi = 0; mi < 4; mi++) {
                const int nb = cx.wm * 64 + mi * 16;
                alo[mi] = *(const uint2*)&As_[(nb + cx.g) * GPITCH + kb];
                ahi[mi] = *(const uint2*)&As_[(nb + cx.g + 8) * GPITCH + kb];
            }
#pragma unroll
            for (int ni = 0; ni < 4; ni++) {
                const int mb = cx.wn * 32 + ni * 8;
                bfp[ni] = *(const uint2*)&Ws_[(mb + cx.g) * GPITCH + kb];
            }
#pragma unroll
            for (int mi = 0; mi < 4; mi++)
#pragma unroll
                for (int ni = 0; ni < 4; ni++)
                    mma_tf32(acc[mi][ni], alo[mi].x, ahi[mi].x, alo[mi].y, ahi[mi].y,
                             bfp[ni].x, bfp[ni].y);
        }

        const int nk = kt + GSTAGES - 1;
        if (nk < KT) {
            const uint32_t sb = (nk % GSTAGES) * GSTAGE_U32 * 4;
            const int k0 = nk * 16;
            cp_async16(aBase + sb + off0, Aptr0 + k0);
            cp_async16(aBase + sb + off1, Aptr1 + k0);
            cp_async16(wBase + sb + off0, Wptr0 + k0);
            cp_async16(wBase + sb + off1, Wptr1 + k0);
        }
        cp_commit();   // uniform group count for wait_group 1
    }
    __syncthreads();
}

__device__ __forceinline__ GemmCtx make_ctx(int t) {
    GemmCtx cx;
    cx.t = t;
    int w = t >> 5;
    cx.wm = w >> 2;
    cx.wn = w & 3;
    int lane = t & 31;
    cx.g  = lane >> 2;
    cx.tg = lane & 3;
    cx.lrr = t >> 2;
    cx.kq  = t & 3;
    return cx;
}

// ---------------- generic GEMM (Wo, FF1, FF2) ----------------
__global__ __launch_bounds__(256, 2)
void gemm_tf32(const float* __restrict__ A, const float* __restrict__ W,
               const float* __restrict__ bias, const float* __restrict__ residual,
               float* __restrict__ C, int N, int M, int K, int flags)
{
    extern __shared__ uint32_t gsm[];
    uint32_t* Asm = gsm;
    uint32_t* Wsm = gsm + GSTAGES * GSTAGE_U32;

    GemmCtx cx = make_ctx(threadIdx.x);
    const int n0 = blockIdx.y * 128, m0 = blockIdx.x * 128;

    float acc[4][4][4];
#pragma unroll
    for (int mi = 0; mi < 4; mi++)
#pragma unroll
        for (int ni = 0; ni < 4; ni++)
#pragma unroll
            for (int c = 0; c < 4; c++) acc[mi][ni][c] = 0.f;

    gemm_mainloop(A + (size_t)(n0 + cx.lrr) * K + cx.kq * 4,
                  A + (size_t)(n0 + cx.lrr + 64) * K + cx.kq * 4,
                  W + (size_t)(m0 + cx.lrr) * K + cx.kq * 4,
                  W + (size_t)(m0 + cx.lrr + 64) * K + cx.kq * 4,
                  Asm, Wsm, cx, K, acc);

    // epilogue: float2 stores (c pairs are adjacent columns)
#pragma unroll
    for (int mi = 0; mi < 4; mi++) {
#pragma unroll
        for (int ni = 0; ni < 4; ni++) {
#pragma unroll
            for (int cr = 0; cr < 2; cr++) {   // cr: 0 -> row g, 1 -> row g+8
                int n = n0 + cx.wm * 64 + mi * 16 + cx.g + cr * 8;
                int m = m0 + cx.wn * 32 + ni * 8 + cx.tg * 2;
                float2 bv2 = *(const float2*)&bias[m];
                float v0 = acc[mi][ni][cr * 2 + 0] + bv2.x;
                float v1 = acc[mi][ni][cr * 2 + 1] + bv2.y;
                if (residual) {
                    float2 rr = *(const float2*)&residual[(size_t)n * M + m];
                    v0 += rr.x; v1 += rr.y;
                }
                if (flags & FLAG_RELU) { v0 = fmaxf(v0, 0.f); v1 = fmaxf(v1, 0.f); }
                float2 ov = { v0, v1 };
                *(float2*)&C[(size_t)n * M + m] = ov;
            }
        }
    }
}

// ---------------- fused QKV GEMM: gridDim.z = 3 selects projection ----------------
__global__ __launch_bounds__(256, 2)
void gemm_qkv(const float* __restrict__ A,
              const float* __restrict__ Wq, const float* __restrict__ Wk, const float* __restrict__ Wv,
              const float* __restrict__ bq, const float* __restrict__ bk, const float* __restrict__ bv,
              float* __restrict__ Cq, float* __restrict__ Ck, float* __restrict__ Cv)
{
    extern __shared__ uint32_t gsm[];
    uint32_t* Asm = gsm;
    uint32_t* Wsm = gsm + GSTAGES * GSTAGE_U32;

    const int z = blockIdx.z;
    const float* W    = (z == 0) ? Wq : (z == 1) ? Wk : Wv;
    const float* bias = (z == 0) ? bq : (z == 1) ? bk : bv;
    float* C          = (z == 0) ? Cq : (z == 1) ? Ck : Cv;

    GemmCtx cx = make_ctx(threadIdx.x);
    const int n0 = blockIdx.y * 128, m0 = blockIdx.x * 128;
    const int K = D_;

    float acc[4][4][4];
#pragma unroll
    for (int mi = 0; mi < 4; mi++)
#pragma unroll
        for (int ni = 0; ni < 4; ni++)
#pragma unroll
            for (int c = 0; c < 4; c++) acc[mi][ni][c] = 0.f;

    gemm_mainloop(A + (size_t)(n0 + cx.lrr) * K + cx.kq * 4,
                  A + (size_t)(n0 + cx.lrr + 64) * K + cx.kq * 4,
                  W + (size_t)(m0 + cx.lrr) * K + cx.kq * 4,
                  W + (size_t)(m0 + cx.lrr + 64) * K + cx.kq * 4,
                  Asm, Wsm, cx, K, acc);

    // epilogue with head-layout scatter: [B,H,S,Dh]; float2 stores (pair stays inside a head)
#pragma unroll
    for (int mi = 0; mi < 4; mi++) {
#pragma unroll
        for (int ni = 0; ni < 4; ni++) {
#pragma unroll
            for (int cr = 0; cr < 2; cr++) {
                int n = n0 + cx.wm * 64 + mi * 16 + cx.g + cr * 8;
                int m = m0 + cx.wn * 32 + ni * 8 + cx.tg * 2;
                float2 bv2 = *(const float2*)&bias[m];
                float v0 = acc[mi][ni][cr * 2 + 0] + bv2.x;
                float v1 = acc[mi][ni][cr * 2 + 1] + bv2.y;
                int b = n >> 11, s = n & 2047;
                int h = m >> 6,  dh = m & 63;
                float2 ov = { v0, v1 };
                *(float2*)&C[(((size_t)(b * H_ + h)) * S_ + s) * DH_ + dh] = ov;
            }
        }
    }
}

// ---------------- flash attention: double-buffered K/V + flag-gated mask (r12 proven) ----------------
#define FAP 72
#define VPP 36
#define KBUF_U32 (64 * FAP)
#define VBUF_U32 (64 * VPP)
#define FA_SMEM ((128 * FAP + 2 * KBUF_U32 + 2 * VBUF_U32) * 4)   // 92160 B

__global__ __launch_bounds__(256, 2)
void flash_tf32(const float* __restrict__ q, const float* __restrict__ k,
                const float* __restrict__ v, const int* __restrict__ mask,
                const uint32_t* __restrict__ mflags, float* __restrict__ ctx)
{
    extern __shared__ uint32_t sm4[];
    uint32_t* Qs   = sm4;                            // [128 q][d] tf32
    uint32_t* Ks   = sm4 + 128 * FAP;                // [2][64 kc][d] raw f32
    uint32_t* VsTb = sm4 + 128 * FAP + 2 * KBUF_U32; // [2][64 d][32 kp] bf16x2

    const int t = threadIdx.x;
    const int w = t >> 5, lane = t & 31;
    const int g = lane >> 2, tg = lane & 3;
    const int qb = w * 16;
    const int bh = blockIdx.y, b = bh >> 4, h = bh & 15;
    const int q0 = blockIdx.x * 128;
    const float* qh = q + (size_t)bh * S_ * DH_;
    const float* kh = k + (size_t)bh * S_ * DH_;
    const float* vh = v + (size_t)bh * S_ * DH_;
    const int* maskb = mask + (size_t)b * S_ * S_;

    const uint32_t ksBase = (uint32_t)__cvta_generic_to_shared(Ks);

    const int krow = t & 63;            // K loader: row, 4 threads/row
    const int kcol = (t >> 6) * 16;
    const int kp = t & 31;              // V loader: keypair
    const int db = (t >> 5) * 8;

    const uint32_t bits0 = mflags[b * S_ + q0 + qb + g];
    const uint32_t bits1 = mflags[b * S_ + q0 + qb + g + 8];

    {   // Q tile (128x64) -> smem tf32 (rna-rounded, loaded once)
        const int lr = t >> 1, lc = (t & 1) * 32;
        const float4* src4 = (const float4*)(qh + (size_t)(q0 + lr) * 64 + lc);
#pragma unroll
        for (int i = 0; i < 8; i++) {
            float4 a = src4[i];
            uint4 u = { f2tf32(a.x), f2tf32(a.y), f2tf32(a.z), f2tf32(a.w) };
            *(uint4*)&Qs[lr * FAP + lc + i * 4] = u;
        }
    }

    // prologue: tile 0 into buffer 0
    {
        const float* ksrc = kh + (size_t)krow * 64 + kcol;
        const uint32_t kdst = ksBase + (krow * FAP + kcol) * 4;
#pragma unroll
        for (int i = 0; i < 4; i++) cp_async16(kdst + i * 16, ksrc + i * 4);
        cp_commit();
        const float4* v0p = (const float4*)(vh + (size_t)(2 * kp) * 64 + db);
        const float4* v1p = (const float4*)(vh + (size_t)(2 * kp + 1) * 64 + db);
        float4 e0 = v0p[0], e1 = v0p[1], o0 = v1p[0], o1 = v1p[1];
        uint32_t* Vb = VsTb;
        Vb[(db + 0) * VPP + kp] = pack_bf16(e0.x, o0.x);
        Vb[(db + 1) * VPP + kp] = pack_bf16(e0.y, o0.y);
        Vb[(db + 2) * VPP + kp] = pack_bf16(e0.z, o0.z);
        Vb[(db + 3) * VPP + kp] = pack_bf16(e0.w, o0.w);
        Vb[(db + 4) * VPP + kp] = pack_bf16(e1.x, o1.x);
        Vb[(db + 5) * VPP + kp] = pack_bf16(e1.y, o1.y);
        Vb[(db + 6) * VPP + kp] = pack_bf16(e1.z, o1.z);
        Vb[(db + 7) * VPP + kp] = pack_bf16(e1.w, o1.w);
        cp_wait0();
    }
    __syncthreads();

    float outac[8][4];
#pragma unroll
    for (int j = 0; j < 8; j++)
#pragma unroll
        for (int c = 0; c < 4; c++) outac[j][c] = 0.f;
    float mrow0 = -1e30f, mrow1 = -1e30f;
    float lrow0 = 0.f, lrow1 = 0.f;

    const int NT = S_ / 64;   // 32
    for (int it = 0; it < NT; it++) {
        const int buf = it & 1;
        const uint32_t* Kb = Ks + buf * KBUF_U32;
        const uint32_t* Vb = VsTb + buf * VBUF_U32;
        const bool more = (it + 1 < NT);

        float4 e0, e1, o0, o1;
        if (more) {
            const int kn = (it + 1) * 64;
            const float* ksrc = kh + (size_t)(kn + krow) * 64 + kcol;
            const uint32_t kdst = ksBase + ((buf ^ 1) * KBUF_U32 + krow * FAP + kcol) * 4;
#pragma unroll
            for (int i = 0; i < 4; i++) cp_async16(kdst + i * 16, ksrc + i * 4);
            cp_commit();
            const float4* v0p = (const float4*)(vh + (size_t)(kn + 2 * kp) * 64 + db);
            const float4* v1p = (const float4*)(vh + (size_t)(kn + 2 * kp + 1) * 64 + db);
            e0 = v0p[0]; e1 = v0p[1]; o0 = v1p[0]; o1 = v1p[1];
        }

        // S = Q K^T  (tf32; conflict-free LDS.64 fragments, k-slot permuted)
        float sa[8][4];
#pragma unroll
        for (int j = 0; j < 8; j++)
#pragma unroll
            for (int c = 0; c < 4; c++) sa[j][c] = 0.f;
#pragma unroll
        for (int kc = 0; kc < 8; kc++) {
            const int kb = kc * 8 + 2 * tg;
            uint2 qlo = *(const uint2*)&Qs[(qb + g) * FAP + kb];
            uint2 qhi = *(const uint2*)&Qs[(qb + g + 8) * FAP + kb];
#pragma unroll
            for (int j = 0; j < 8; j++) {
                uint2 kf = *(const uint2*)&Kb[(j * 8 + g) * FAP + kb];
                mma_tf32(sa[j], qlo.x, qhi.x, qlo.y, qhi.y, kf.x, kf.y);
            }
        }

        if (more) {
            uint32_t* Vn = VsTb + (buf ^ 1) * VBUF_U32;
            Vn[(db + 0) * VPP + kp] = pack_bf16(e0.x, o0.x);
            Vn[(db + 1) * VPP + kp] = pack_bf16(e0.y, o0.y);
            Vn[(db + 2) * VPP + kp] = pack_bf16(e0.z, o0.z);
            Vn[(db + 3) * VPP + kp] = pack_bf16(e0.w, o0.w);
            Vn[(db + 4) * VPP + kp] = pack_bf16(e1.x, o1.x);
            Vn[(db + 5) * VPP + kp] = pack_bf16(e1.y, o1.y);
            Vn[(db + 6) * VPP + kp] = pack_bf16(e1.z, o1.z);
            Vn[(db + 7) * VPP + kp] = pack_bf16(e1.w, o1.w);
        }

        // scale + mask (flag-gated)
        const bool allok = (((bits0 >> it) & (bits1 >> it)) & 1u) != 0u;
        if (allok) {
#pragma unroll
            for (int j = 0; j < 8; j++) {
                sa[j][0] *= 0.125f; sa[j][1] *= 0.125f;
                sa[j][2] *= 0.125f; sa[j][3] *= 0.125f;
            }
        } else {
            const int k0 = it * 64;
            const size_t mrow_a = (size_t)(q0 + qb + g) * S_ + k0;
            const size_t mrow_b = (size_t)(q0 + qb + g + 8) * S_ + k0;
#pragma unroll
            for (int j = 0; j < 8; j++) {
                int col = j * 8 + tg * 2;
                int2 m0 = *(const int2*)&maskb[mrow_a + col];
                int2 m1 = *(const int2*)&maskb[mrow_b + col];
                sa[j][0] = m0.x ? sa[j][0] * 0.125f : -1e9f;
                sa[j][1] = m0.y ? sa[j][1] * 0.125f : -1e9f;
                sa[j][2] = m1.x ? sa[j][2] * 0.125f : -1e9f;
                sa[j][3] = m1.y ? sa[j][3] * 0.125f : -1e9f;
            }
        }

        // online softmax (rows g, g+8), quad reduce
        float mx0 = -1e30f, mx1 = -1e30f;
#pragma unroll
        for (int j = 0; j < 8; j++) {
            mx0 = fmaxf(mx0, fmaxf(sa[j][0], sa[j][1]));
            mx1 = fmaxf(mx1, fmaxf(sa[j][2], sa[j][3]));
        }
        mx0 = fmaxf(mx0, __shfl_xor_sync(0xffffffffu, mx0, 1));
        mx0 = fmaxf(mx0, __shfl_xor_sync(0xffffffffu, mx0, 2));
        mx1 = fmaxf(mx1, __shfl_xor_sync(0xffffffffu, mx1, 1));
        mx1 = fmaxf(mx1, __shfl_xor_sync(0xffffffffu, mx1, 2));

        float mn0 = fmaxf(mrow0, mx0), mn1 = fmaxf(mrow1, mx1);
        float cr0 = fast_exp(mrow0 - mn0), cr1 = fast_exp(mrow1 - mn1);
        mrow0 = mn0; mrow1 = mn1;

        float rs0 = 0.f, rs1 = 0.f;
#pragma unroll
        for (int j = 0; j < 8; j++) {
            sa[j][0] = fast_exp(sa[j][0] - mn0);
            sa[j][1] = fast_exp(sa[j][1] - mn0);
            sa[j][2] = fast_exp(sa[j][2] - mn1);
            sa[j][3] = fast_exp(sa[j][3] - mn1);
            rs0 += sa[j][0] + sa[j][1];
            rs1 += sa[j][2] + sa[j][3];
        }
        rs0 += __shfl_xor_sync(0xffffffffu, rs0, 1);
        rs0 += __shfl_xor_sync(0xffffffffu, rs0, 2);
        rs1 += __shfl_xor_sync(0xffffffffu, rs1, 1);
        rs1 += __shfl_xor_sync(0xffffffffu, rs1, 2);
        lrow0 = lrow0 * cr0 + rs0;
        lrow1 = lrow1 * cr1 + rs1;

#pragma unroll
        for (int j = 0; j < 8; j++) {
            outac[j][0] *= cr0; outac[j][1] *= cr0;
            outac[j][2] *= cr1; outac[j][3] *= cr1;
        }

        // out += P V  — P packed from registers (bf16), V from current buffer
#pragma unroll
        for (int s = 0; s < 4; s++) {
            uint32_t a0 = pack_bf16(sa[2*s][0],   sa[2*s][1]);
            uint32_t a1 = pack_bf16(sa[2*s][2],   sa[2*s][3]);
            uint32_t a2 = pack_bf16(sa[2*s+1][0], sa[2*s+1][1]);
            uint32_t a3 = pack_bf16(sa[2*s+1][2], sa[2*s+1][3]);
            const int kpb = 8 * s;
#pragma unroll
            for (int j = 0; j < 8; j++) {
                uint32_t b0 = Vb[(j * 8 + g) * VPP + kpb + tg];
                uint32_t b1 = Vb[(j * 8 + g) * VPP + kpb + tg + 4];
                mma_bf16(outac[j], a0, a1, a2, a3, b0, b1);
            }
        }

        if (more) cp_wait0();
        __syncthreads();
    }

    // epilogue
    float i0 = 1.f / lrow0, i1 = 1.f / lrow1;
    const int nrow = b * S_ + q0 + qb + g;
    const int hb = h * 64;
#pragma unroll
    for (int j = 0; j < 8; j++) {
        float2 o0 = { outac[j][0] * i0, outac[j][1] * i0 };
        *(float2*)&ctx[(size_t)nrow * D_ + hb + j * 8 + tg * 2] = o0;
        float2 o1 = { outac[j][2] * i1, outac[j][3] * i1 };
        *(float2*)&ctx[(size_t)(nrow + 8) * D_ + hb + j * 8 + tg * 2] = o1;
    }
}

// ---------------- layer norm (torch semantics: ddof=1, eps on std) ----------------
__global__ void layernorm_kernel(const float* __restrict__ x, const float* __restrict__ alpha,
                                 const float* __restrict__ beta, float* __restrict__ out)
{
    const int row = blockIdx.x;
    const int t = threadIdx.x;
    const float4* xr = (const float4*)(x + (size_t)row * D_);
    float4 v = xr[t];
    float sum = v.x + v.y + v.z + v.w;
    float sq  = v.x * v.x + v.y * v.y + v.z * v.z + v.w * v.w;

    __shared__ float ssum[8], ssq[8];
#pragma unroll
    for (int off = 16; off; off >>= 1) {
        sum += __shfl_xor_sync(0xffffffffu, sum, off);
        sq  += __shfl_xor_sync(0xffffffffu, sq, off);
    }
    int warp = t >> 5, lane = t & 31;
    if (lane == 0) { ssum[warp] = sum; ssq[warp] = sq; }
    __syncthreads();
    float tsum = 0.f, tsq = 0.f;
#pragma unroll
    for (int w = 0; w < 8; w++) { tsum += ssum[w]; tsq += ssq[w]; }

    float mean = tsum * (1.f / D_);
    float var  = (tsq - (float)D_ * mean * mean) * (1.f / (D_ - 1));
    float std_ = sqrtf(fmaxf(var, 0.f));
    float inv  = 1.f / (std_ + EPS_);

    const float4* av = (const float4*)alpha;
    const float4* bv = (const float4*)beta;
    float4 a = av[t], bb = bv[t];
    float4 o;
    o.x = a.x * (v.x - mean) * inv + bb.x;
    o.y = a.y * (v.y - mean) * inv + bb.y;
    o.z = a.z * (v.z - mean) * inv + bb.z;
    o.w = a.w * (v.w - mean) * inv + bb.w;
    ((float4*)(out + (size_t)row * D_))[t] = o;
}

// ---------------- launch ----------------
extern "C" void kernel_launch(void* const* d_in, const int* in_sizes, int n_in,
                              void* d_out, int out_size)
{
    const float* src = (const float*)d_in[0];
    const int*   mask = (const int*)d_in[1];
    const float* Wq = (const float*)d_in[2];
    const float* bq = (const float*)d_in[3];
    const float* Wk = (const float*)d_in[4];
    const float* bk = (const float*)d_in[5];
    const float* Wv = (const float*)d_in[6];
    const float* bv = (const float*)d_in[7];
    const float* Wo = (const float*)d_in[8];
    const float* bo = (const float*)d_in[9];
    const float* W1 = (const float*)d_in[10];
    const float* b1 = (const float*)d_in[11];
    const float* W2 = (const float*)d_in[12];
    const float* b2 = (const float*)d_in[13];
    const float* a1 = (const float*)d_in[14];
    const float* be1 = (const float*)d_in[15];
    const float* a2 = (const float*)d_in[16];
    const float* be2 = (const float*)d_in[17];
    float* out = (float*)d_out;

    void *pq, *pk, *pv, *pctx, *px0, *px1, *pff, *pmf;
    cudaGetSymbolAddress(&pq, g_q);
    cudaGetSymbolAddress(&pk, g_k);
    cudaGetSymbolAddress(&pv, g_v);
    cudaGetSymbolAddress(&pctx, g_ctx);
    cudaGetSymbolAddress(&px0, g_x0);
    cudaGetSymbolAddress(&px1, g_x1);
    cudaGetSymbolAddress(&pff, g_ff);
    cudaGetSymbolAddress(&pmf, g_mflags);

    cudaFuncSetAttribute(flash_tf32, cudaFuncAttributeMaxDynamicSharedMemorySize, FA_SMEM);
    cudaFuncSetAttribute(gemm_tf32, cudaFuncAttributeMaxDynamicSharedMemorySize, GEMM_SMEM);
    cudaFuncSetAttribute(gemm_qkv, cudaFuncAttributeMaxDynamicSharedMemorySize, GEMM_SMEM);

    dim3 blk(256);
    dim3 gD(D_ / 128, N_ / 128);         // (8, 32)
    dim3 gQKV(D_ / 128, N_ / 128, 3);    // (8, 32, 3) — fused QKV
    dim3 gFF(FF_ / 128, N_ / 128);       // (16, 32)

    // mask flags (independent of QKV; tiny)
    maskflags_kernel<<<(N_ * 32 + 255) / 256, blk>>>(mask, (uint32_t*)pmf);

    // fused QKV projections, stored directly in [B,H,S,Dh] layout
    gemm_qkv<<<gQKV, blk, GEMM_SMEM>>>(src, Wq, Wk, Wv, bq, bk, bv,
                                       (float*)pq, (float*)pk, (float*)pv);

    // attention -> ctx in [N, D] layout
    flash_tf32<<<dim3(S_ / 128, B_ * H_), dim3(256), FA_SMEM>>>(
        (const float*)pq, (const float*)pk, (const float*)pv, mask,
        (const uint32_t*)pmf, (float*)pctx);

    // output projection + residual(src)
    gemm_tf32<<<gD, blk, GEMM_SMEM>>>((const float*)pctx, Wo, bo, src, (float*)px0, N_, D_, D_, 0);

    // norm1
    layernorm_kernel<<<N_, blk>>>((const float*)px0, a1, be1, (float*)px1);

    // FFN
    gemm_tf32<<<gFF, blk, GEMM_SMEM>>>((const float*)px1, W1, b1, nullptr, (float*)pff, N_, FF_, D_, FLAG_RELU);
    gemm_tf32<<<gD, blk, GEMM_SMEM>>>((const float*)pff, W2, b2, (const float*)px1, (float*)px0, N_, D_, FF_, 0);

    // norm2 -> out
    layernorm_kernel<<<N_, blk>>>((const float*)px0, a2, be2, out);
}